// round 10
// baseline (speedup 1.0000x reference)
#include <cuda_runtime.h>
#include <math.h>
#include <stdint.h>

// Problem constants
#define BB    64
#define TT    2048
#define NIN   4
#define H0    64
#define DD    128
#define HDD   256
#define DEPTH 4
#define MM    (BB * TT)   // 131072 rows

// Scratch (device globals; allocation-free per harness rules)
__device__ float g_x[(size_t)MM * DD];    // 64 MB  running features [B,T,D]
__device__ float g_h[(size_t)MM * HDD];   // 128 MB hidden / spikes   [B,T,HD]
__device__ float g_t[(size_t)MM * DD];    // 64 MB  temp              [B,T,D]

// ---------------------------------------------------------------------------
// Packed f32x2 helpers (sm_103a). Each lane is an independent, correctly
// rounded fp32 op — bit-identical to scalar fmaf per output.
// ---------------------------------------------------------------------------
__device__ __forceinline__ unsigned long long pack_dup(float a) {
    unsigned long long r;
    asm("mov.b64 %0, {%1, %1};" : "=l"(r) : "f"(a));
    return r;
}
__device__ __forceinline__ void unpack2(unsigned long long v, float& lo, float& hi) {
    asm("mov.b64 {%0, %1}, %2;" : "=f"(lo), "=f"(hi) : "l"(v));
}
#define FFMA2(acc, a2, b2) \
    asm("fma.rn.f32x2 %0, %1, %2, %0;" : "+l"(acc) : "l"(a2), "l"(b2))

// ---------------------------------------------------------------------------
// XLA erf f32 (rational poly, clamp +-4, unfused mul/add, rounded divide)
// ---------------------------------------------------------------------------
__device__ __forceinline__ float xla_erf(float x) {
    x = fminf(fmaxf(x, -4.0f), 4.0f);
    float x2 = __fmul_rn(x, x);
    float p = -2.72614225801306e-10f;
    p = __fadd_rn(__fmul_rn(p, x2),  2.77068142495902e-08f);
    p = __fadd_rn(__fmul_rn(p, x2), -2.10102402082508e-06f);
    p = __fadd_rn(__fmul_rn(p, x2), -5.69250639462346e-05f);
    p = __fadd_rn(__fmul_rn(p, x2), -7.34990630326855e-04f);
    p = __fadd_rn(__fmul_rn(p, x2), -2.95459980854025e-03f);
    p = __fadd_rn(__fmul_rn(p, x2), -1.60960333262415e-02f);
    p = __fmul_rn(x, p);
    float q = -1.45660718464996e-05f;
    q = __fadd_rn(__fmul_rn(q, x2), -2.13374055278905e-04f);
    q = __fadd_rn(__fmul_rn(q, x2), -1.68282697438203e-03f);
    q = __fadd_rn(__fmul_rn(q, x2), -7.37332916720468e-03f);
    q = __fadd_rn(__fmul_rn(q, x2), -1.42647390514189e-02f);
    return __fdiv_rn(p, q);
}

__device__ __forceinline__ float gelu_exact(float x) {
    float u = __fdiv_rn(x, 1.4142135623730951f);
    float e = xla_erf(u);
    return __fmul_rn(__fmul_rn(x, __fadd_rn(e, 1.0f)), 0.5f);
}

// ---------------------------------------------------------------------------
// Projector stage 1: g1[r,j] = gelu(hist[r,:4] @ pw1[:,j] + pb1[j])
// ---------------------------------------------------------------------------
__global__ void proj1_kernel(const float* __restrict__ hist,
                             const float* __restrict__ pw1,
                             const float* __restrict__ pb1,
                             float* __restrict__ g1)
{
    long idx = (long)blockIdx.x * blockDim.x + threadIdx.x;  // M*64 total
    long r = idx >> 6;
    int  j = (int)(idx & 63);
    const float* hp = hist + r * NIN;
    float acc = 0.0f;
    acc = fmaf(__ldg(hp + 0), __ldg(&pw1[0 * H0 + j]), acc);
    acc = fmaf(__ldg(hp + 1), __ldg(&pw1[1 * H0 + j]), acc);
    acc = fmaf(__ldg(hp + 2), __ldg(&pw1[2 * H0 + j]), acc);
    acc = fmaf(__ldg(hp + 3), __ldg(&pw1[3 * H0 + j]), acc);
    float h = __fadd_rn(acc, __ldg(&pb1[j]));
    g1[idx] = gelu_exact(h);
}

// ---------------------------------------------------------------------------
// Fused GEMM (+bias) (+LayerNorm): FFMA2 mainloop + CPU-exact epilogue.
//  - per-output: single ascending-k fp32 FMA chain (bit-identical to R7/R9)
//  - LN: strict sequential left-fold per row (one thread), rstd = 1/sqrt
// CTA: 64 rows x N cols, 256 threads = 8 warps.
// Mainloop thread tile: 4 rows (rg=tid&15) x CT cols (cg=tid>>4, CT=N/16).
// A stored pre-duplicated {a,a} in smem -> LDS.64 packed operand, no MOVs.
// Warp = 16 rowgroups x 2 colgroups: B loads broadcast, A conflict-free.
// ---------------------------------------------------------------------------
template<int N, int K, bool DO_LN>
__global__ __launch_bounds__(256, 2)
void gemm_ln_f2(const float* __restrict__ A, const float* __restrict__ W,
                const float* __restrict__ bias,
                const float* __restrict__ gamma, const float* __restrict__ beta,
                float* __restrict__ out)
{
    constexpr int BM = 64, BK = 32;
    constexpr int CT = N / 16;       // cols per thread (16 or 8)
    constexpr int CP = CT / 2;       // packed col-pairs (8 or 4)
    constexpr int NP = N + 1;
    constexpr int ASTR = BK + 1;     // A row stride in float2 units (33)
    extern __shared__ float sm[];
    unsigned long long* As2 = (unsigned long long*)sm;   // [64][33] packed {a,a}
    float* Bs = sm + BM * ASTR * 2;                      // [32][N]

    const int tid = threadIdx.x;
    const int rg = tid & 15, cg = tid >> 4;
    const int r0t = rg * 4;          // first of 4 owned rows
    const int c0 = cg * CT;          // first of CT owned cols
    const long row0 = (long)blockIdx.x * BM;

    unsigned long long acc[4][CP];
#pragma unroll
    for (int i = 0; i < 4; ++i)
#pragma unroll
        for (int j = 0; j < CP; ++j) acc[i][j] = 0ull;

    for (int kk = 0; kk < K; kk += BK) {
        // A tile 64x32, stored duplicated {a,a}
#pragma unroll
        for (int it = 0; it < 2; ++it) {
            int e4 = tid + it * 256;
            int r  = e4 >> 3;
            int k4 = (e4 & 7) << 2;
            float4 v = *(const float4*)&A[(row0 + r) * K + kk + k4];
            unsigned long long* d = &As2[r * ASTR + k4];
            d[0] = pack_dup(v.x); d[1] = pack_dup(v.y);
            d[2] = pack_dup(v.z); d[3] = pack_dup(v.w);
        }
        // B tile 32xN
        constexpr int B4 = BK * N / 4;
#pragma unroll
        for (int it = 0; it < B4 / 256; ++it) {
            int e4 = tid + it * 256;
            int kb = e4 / (N / 4);
            int c4 = (e4 % (N / 4)) << 2;
            *(float4*)&Bs[kb * N + c4] = *(const float4*)&W[(long)(kk + kb) * N + c4];
        }
        __syncthreads();
#pragma unroll
        for (int k = 0; k < BK; ++k) {
            unsigned long long a2[4];
#pragma unroll
            for (int i = 0; i < 4; ++i) a2[i] = As2[(r0t + i) * ASTR + k];
            unsigned long long b2[CP];
#pragma unroll
            for (int j = 0; j < CP; j += 2) {
                ulonglong2 p = *(const ulonglong2*)&Bs[k * N + c0 + 2 * j];
                b2[j] = p.x; b2[j + 1] = p.y;
            }
#pragma unroll
            for (int i = 0; i < 4; ++i)
#pragma unroll
                for (int j = 0; j < CP; ++j) FFMA2(acc[i][j], a2[i], b2[j]);
        }
        __syncthreads();
    }

    if (!DO_LN) {
        // bias + direct store from registers
#pragma unroll
        for (int i = 0; i < 4; ++i) {
            float v[CT];
#pragma unroll
            for (int j = 0; j < CP; ++j) unpack2(acc[i][j], v[2 * j], v[2 * j + 1]);
#pragma unroll
            for (int j = 0; j < CT; ++j)
                v[j] = __fadd_rn(v[j], __ldg(&bias[c0 + j]));
            long r = row0 + r0t + i;
#pragma unroll
            for (int j = 0; j < CT; j += 4)
                *(float4*)&out[r * N + c0 + j] =
                    make_float4(v[j], v[j + 1], v[j + 2], v[j + 3]);
        }
        return;
    }

    // stage acc+bias to smem [64][NP] (reuses mainloop smem)
    float* S     = sm;
    float* meanv = sm + BM * NP;          // [64]
    float* rstdv = meanv + BM;            // [64]
#pragma unroll
    for (int i = 0; i < 4; ++i) {
        int r = r0t + i;
        float v[CT];
#pragma unroll
        for (int j = 0; j < CP; ++j) unpack2(acc[i][j], v[2 * j], v[2 * j + 1]);
#pragma unroll
        for (int j = 0; j < CT; ++j)
            S[r * NP + c0 + j] = __fadd_rn(v[j], __ldg(&bias[c0 + j]));
    }
    __syncthreads();

    // Phase A: one thread per row, strict sequential left-fold (XLA:CPU).
    if (tid < BM) {
        const float* row = &S[tid * NP];
        float s = 0.0f;
        for (int j = 0; j < N; ++j) s = __fadd_rn(s, row[j]);
        float mean = __fdiv_rn(s, (float)N);   // /128, /256: exact
        float q = 0.0f;
        for (int j = 0; j < N; ++j) {
            float d = __fsub_rn(row[j], mean);
            q = __fadd_rn(q, __fmul_rn(d, d));
        }
        float var = __fdiv_rn(q, (float)N);
        float rstd = __fdiv_rn(1.0f, __fsqrt_rn(__fadd_rn(var, 1e-5f)));
        meanv[tid] = mean;
        rstdv[tid] = rstd;
    }
    __syncthreads();

    // Phase B: cooperative normalize + coalesced store. 4 threads per row.
    {
        const int r = tid >> 2, qq = tid & 3, cc0 = qq * (N / 4);
        float mean = meanv[r], rstd = rstdv[r];
#pragma unroll
        for (int j = 0; j < N / 4; j += 4) {
            float o[4];
#pragma unroll
            for (int e = 0; e < 4; ++e) {
                int c = cc0 + j + e;
                float v = S[r * NP + c];
                float t = __fmul_rn(__fsub_rn(v, mean), rstd);
                t = __fmul_rn(t, __ldg(&gamma[c]));
                o[e] = __fadd_rn(t, __ldg(&beta[c]));
            }
            *(float4*)&out[(row0 + r) * N + cc0 + j] = make_float4(o[0], o[1], o[2], o[3]);
        }
    }
}

// ---------------------------------------------------------------------------
// LIF scan over T (in-place: membrane input -> spikes). FEAT = 256.
// Exact: v = v + (x-v)*0.5, spike v>=1, hard reset 0. U=32 prefetch.
// block 64 / grid 256 to cover all 148 SMs.
// ---------------------------------------------------------------------------
__global__ __launch_bounds__(64) void lif_spike_kernel(float* h)
{
    const int lane = blockIdx.x * blockDim.x + threadIdx.x;  // 0..B*HD-1
    const int b = lane >> 8;
    const int d = lane & 255;
    float* p = h + (long)b * TT * HDD + d;

    constexpr int U = 32;
    float cur[U];
#pragma unroll
    for (int u = 0; u < U; ++u) cur[u] = p[(long)u * HDD];

    float v = 0.0f;
    for (int t0 = 0; t0 < TT; t0 += U) {
        float nxt[U];
        if (t0 + U < TT) {
#pragma unroll
            for (int u = 0; u < U; ++u) nxt[u] = p[(long)(t0 + U + u) * HDD];
        }
#pragma unroll
        for (int u = 0; u < U; ++u) {
            float dd = __fsub_rn(cur[u], v);
            v = __fadd_rn(v, __fmul_rn(dd, 0.5f));
            float s = (v >= 1.0f) ? 1.0f : 0.0f;
            v = (v >= 1.0f) ? 0.0f : v;
            p[(long)(t0 + u) * HDD] = s;
        }
#pragma unroll
        for (int u = 0; u < U; ++u) cur[u] = nxt[u];
    }
}

// ---------------------------------------------------------------------------
// LIF scan + residual accumulate into x; write d_out at t = T-1. FEAT = 128.
// ---------------------------------------------------------------------------
__global__ __launch_bounds__(64) void lif_resid_kernel(const float* __restrict__ in,
                                                       float* x, float* dout)
{
    const int lane = blockIdx.x * blockDim.x + threadIdx.x;  // 0..B*D-1
    const int b = lane >> 7;
    const int d = lane & 127;
    const float* pi = in + (long)b * TT * DD + d;
    float*       px = x  + (long)b * TT * DD + d;

    constexpr int U = 32;
    float ci[U], cx[U];
#pragma unroll
    for (int u = 0; u < U; ++u) { ci[u] = pi[(long)u * DD]; cx[u] = px[(long)u * DD]; }

    float v = 0.0f;
    for (int t0 = 0; t0 < TT; t0 += U) {
        float ni[U], nx[U];
        if (t0 + U < TT) {
#pragma unroll
            for (int u = 0; u < U; ++u) {
                ni[u] = pi[(long)(t0 + U + u) * DD];
                nx[u] = px[(long)(t0 + U + u) * DD];
            }
        }
#pragma unroll
        for (int u = 0; u < U; ++u) {
            float dd = __fsub_rn(ci[u], v);
            v = __fadd_rn(v, __fmul_rn(dd, 0.5f));
            float s = (v >= 1.0f) ? 1.0f : 0.0f;
            v = (v >= 1.0f) ? 0.0f : v;
            float xv = __fadd_rn(cx[u], s);
            px[(long)(t0 + u) * DD] = xv;
            if (t0 + u == TT - 1) dout[b * DD + d] = xv;
        }
#pragma unroll
        for (int u = 0; u < U; ++u) { ci[u] = ni[u]; cx[u] = nx[u]; }
    }
}

// ---------------------------------------------------------------------------
// Launch
// ---------------------------------------------------------------------------
extern "C" void kernel_launch(void* const* d_in, const int* in_sizes, int n_in,
                              void* d_out, int out_size)
{
    const float* hist  = (const float*)d_in[0];
    const float* pw1   = (const float*)d_in[1];
    const float* pb1   = (const float*)d_in[2];
    const float* pw2   = (const float*)d_in[3];
    const float* pb2   = (const float*)d_in[4];
    const float* fc1_w = (const float*)d_in[5];
    const float* fc1_b = (const float*)d_in[6];
    const float* n1_g  = (const float*)d_in[7];
    const float* n1_b  = (const float*)d_in[8];
    const float* fc2_w = (const float*)d_in[9];
    const float* fc2_b = (const float*)d_in[10];
    const float* n2_g  = (const float*)d_in[11];
    const float* n2_b  = (const float*)d_in[12];
    float* out = (float*)d_out;

    float *px, *ph, *pt;
    cudaGetSymbolAddress((void**)&px, g_x);
    cudaGetSymbolAddress((void**)&ph, g_h);
    cudaGetSymbolAddress((void**)&pt, g_t);

    // dynamic smem: max(mainloop = As2 16896 + Bs 128*N, staging = (64*NP+128)*4)
    const int smem128 = 64 * (32 + 1) * 8 + 32 * 128 * 4;        // 33280
    const int smem128s = (64 * 129 + 128) * 4;                   // 33536
    const int sA = (smem128 > smem128s) ? smem128 : smem128s;    // 33536
    const int smem256 = (64 * 257 + 128) * 4;                    // 66304 (> mainloop 49664)
    cudaFuncSetAttribute(gemm_ln_f2<DD, H0, false>,
                         cudaFuncAttributeMaxDynamicSharedMemorySize, sA);
    cudaFuncSetAttribute(gemm_ln_f2<HDD, DD, true>,
                         cudaFuncAttributeMaxDynamicSharedMemorySize, smem256);
    cudaFuncSetAttribute(gemm_ln_f2<DD, HDD, true>,
                         cudaFuncAttributeMaxDynamicSharedMemorySize, sA);

    // Projector: hist@pw1 -> gelu -> @pw2 (+biases) -> g_x
    proj1_kernel<<<(MM * H0) / 256, 256>>>(hist, pw1, pb1, pt);
    gemm_ln_f2<DD, H0, false><<<MM / 64, 256, sA>>>(pt, pw2, pb2, nullptr, nullptr, px);

    for (int i = 0; i < DEPTH; ++i) {
        gemm_ln_f2<HDD, DD, true><<<MM / 64, 256, smem256>>>(
            px, fc1_w + (long)i * DD * HDD, fc1_b + i * HDD,
            n1_g + i * HDD, n1_b + i * HDD, ph);
        lif_spike_kernel<<<(BB * HDD) / 64, 64>>>(ph);
        gemm_ln_f2<DD, HDD, true><<<MM / 64, 256, sA>>>(
            ph, fc2_w + (long)i * HDD * DD, fc2_b + i * DD,
            n2_g + i * DD, n2_b + i * DD, pt);
        lif_resid_kernel<<<(BB * DD) / 64, 64>>>(pt, px, out);
    }
}

// round 12
// speedup vs baseline: 1.1431x; 1.1431x over previous
#include <cuda_runtime.h>
#include <math.h>
#include <stdint.h>

// Problem constants
#define BB    64
#define TT    2048
#define NIN   4
#define H0    64
#define DD    128
#define HDD   256
#define DEPTH 4
#define MM    (BB * TT)   // 131072 rows

// Scratch (device globals; allocation-free per harness rules)
__device__ float g_x[(size_t)MM * DD];    // 64 MB  running features [B,T,D]
__device__ float g_h[(size_t)MM * HDD];   // 128 MB hidden / spikes   [B,T,HD]
__device__ float g_t[(size_t)MM * DD];    // 64 MB  temp              [B,T,D]

// ---------------------------------------------------------------------------
// Packed f32x2 helpers (sm_103a). Each lane is an independent, correctly
// rounded fp32 op — bit-identical to scalar fmaf per output.
// ---------------------------------------------------------------------------
__device__ __forceinline__ unsigned long long pack_dup(float a) {
    unsigned long long r;
    asm("mov.b64 %0, {%1, %1};" : "=l"(r) : "f"(a));
    return r;
}
__device__ __forceinline__ void unpack2(unsigned long long v, float& lo, float& hi) {
    asm("mov.b64 {%0, %1}, %2;" : "=f"(lo), "=f"(hi) : "l"(v));
}
#define FFMA2(acc, a2, b2) \
    asm("fma.rn.f32x2 %0, %1, %2, %0;" : "+l"(acc) : "l"(a2), "l"(b2))

// ---------------------------------------------------------------------------
// XLA erf f32 (rational poly, clamp +-4, unfused mul/add, rounded divide)
// ---------------------------------------------------------------------------
__device__ __forceinline__ float xla_erf(float x) {
    x = fminf(fmaxf(x, -4.0f), 4.0f);
    float x2 = __fmul_rn(x, x);
    float p = -2.72614225801306e-10f;
    p = __fadd_rn(__fmul_rn(p, x2),  2.77068142495902e-08f);
    p = __fadd_rn(__fmul_rn(p, x2), -2.10102402082508e-06f);
    p = __fadd_rn(__fmul_rn(p, x2), -5.69250639462346e-05f);
    p = __fadd_rn(__fmul_rn(p, x2), -7.34990630326855e-04f);
    p = __fadd_rn(__fmul_rn(p, x2), -2.95459980854025e-03f);
    p = __fadd_rn(__fmul_rn(p, x2), -1.60960333262415e-02f);
    p = __fmul_rn(x, p);
    float q = -1.45660718464996e-05f;
    q = __fadd_rn(__fmul_rn(q, x2), -2.13374055278905e-04f);
    q = __fadd_rn(__fmul_rn(q, x2), -1.68282697438203e-03f);
    q = __fadd_rn(__fmul_rn(q, x2), -7.37332916720468e-03f);
    q = __fadd_rn(__fmul_rn(q, x2), -1.42647390514189e-02f);
    return __fdiv_rn(p, q);
}

__device__ __forceinline__ float gelu_exact(float x) {
    float u = __fdiv_rn(x, 1.4142135623730951f);
    float e = xla_erf(u);
    return __fmul_rn(__fmul_rn(x, __fadd_rn(e, 1.0f)), 0.5f);
}

// ---------------------------------------------------------------------------
// Projector stage 1: g1[r,j] = gelu(hist[r,:4] @ pw1[:,j] + pb1[j])
// ---------------------------------------------------------------------------
__global__ void proj1_kernel(const float* __restrict__ hist,
                             const float* __restrict__ pw1,
                             const float* __restrict__ pb1,
                             float* __restrict__ g1)
{
    long idx = (long)blockIdx.x * blockDim.x + threadIdx.x;  // M*64 total
    long r = idx >> 6;
    int  j = (int)(idx & 63);
    const float* hp = hist + r * NIN;
    float acc = 0.0f;
    acc = fmaf(__ldg(hp + 0), __ldg(&pw1[0 * H0 + j]), acc);
    acc = fmaf(__ldg(hp + 1), __ldg(&pw1[1 * H0 + j]), acc);
    acc = fmaf(__ldg(hp + 2), __ldg(&pw1[2 * H0 + j]), acc);
    acc = fmaf(__ldg(hp + 3), __ldg(&pw1[3 * H0 + j]), acc);
    float h = __fadd_rn(acc, __ldg(&pb1[j]));
    g1[idx] = gelu_exact(h);
}

// ---------------------------------------------------------------------------
// Fused GEMM (+bias) (+LayerNorm): FFMA2 mainloop + CPU-exact epilogue.
//  - per-output: single ascending-k fp32 FMA chain (bit-identical to R7/R9)
//  - LN: strict sequential left-fold per row (one thread), rstd = 1/sqrt
// CTA: 64 rows x N cols, 256 threads = 8 warps.
// Mainloop thread tile: 4 rows STRIDED (rg, rg+16, rg+32, rg+48; rg=tid&15)
// x CT cols (cg=tid>>4, CT=N/16). Strided rows make A LDS.64 conflict-free:
// bank-pair (2*rg + 2k) mod 32 distinct across the 16 rg lanes of a half-warp.
// A stored pre-duplicated {a,a} in smem -> LDS.64 packed operand, no MOVs.
// B loads are half-warp broadcasts (16 lanes share cg).
// ---------------------------------------------------------------------------
template<int N, int K, bool DO_LN>
__global__ __launch_bounds__(256, 2)
void gemm_ln_f2(const float* __restrict__ A, const float* __restrict__ W,
                const float* __restrict__ bias,
                const float* __restrict__ gamma, const float* __restrict__ beta,
                float* __restrict__ out)
{
    constexpr int BM = 64, BK = 32;
    constexpr int CT = N / 16;       // cols per thread (16 or 8)
    constexpr int CP = CT / 2;       // packed col-pairs (8 or 4)
    constexpr int NP = N + 1;
    constexpr int ASTR = BK + 1;     // A row stride in float2 units (33)
    extern __shared__ float sm[];
    unsigned long long* As2 = (unsigned long long*)sm;   // [64][33] packed {a,a}
    float* Bs = sm + BM * ASTR * 2;                      // [32][N]

    const int tid = threadIdx.x;
    const int rg = tid & 15, cg = tid >> 4;
    const int c0 = cg * CT;          // first of CT owned cols
    const long row0 = (long)blockIdx.x * BM;

    unsigned long long acc[4][CP];
#pragma unroll
    for (int i = 0; i < 4; ++i)
#pragma unroll
        for (int j = 0; j < CP; ++j) acc[i][j] = 0ull;

    for (int kk = 0; kk < K; kk += BK) {
        // A tile 64x32, stored duplicated {a,a}
#pragma unroll
        for (int it = 0; it < 2; ++it) {
            int e4 = tid + it * 256;
            int r  = e4 >> 3;
            int k4 = (e4 & 7) << 2;
            float4 v = *(const float4*)&A[(row0 + r) * K + kk + k4];
            unsigned long long* d = &As2[r * ASTR + k4];
            d[0] = pack_dup(v.x); d[1] = pack_dup(v.y);
            d[2] = pack_dup(v.z); d[3] = pack_dup(v.w);
        }
        // B tile 32xN
        constexpr int B4 = BK * N / 4;
#pragma unroll
        for (int it = 0; it < B4 / 256; ++it) {
            int e4 = tid + it * 256;
            int kb = e4 / (N / 4);
            int c4 = (e4 % (N / 4)) << 2;
            *(float4*)&Bs[kb * N + c4] = *(const float4*)&W[(long)(kk + kb) * N + c4];
        }
        __syncthreads();
#pragma unroll
        for (int k = 0; k < BK; ++k) {
            unsigned long long a2[4];
#pragma unroll
            for (int i = 0; i < 4; ++i) a2[i] = As2[(rg + 16 * i) * ASTR + k];
            unsigned long long b2[CP];
#pragma unroll
            for (int j = 0; j < CP; j += 2) {
                ulonglong2 p = *(const ulonglong2*)&Bs[k * N + c0 + 2 * j];
                b2[j] = p.x; b2[j + 1] = p.y;
            }
#pragma unroll
            for (int i = 0; i < 4; ++i)
#pragma unroll
                for (int j = 0; j < CP; ++j) FFMA2(acc[i][j], a2[i], b2[j]);
        }
        __syncthreads();
    }

    if (!DO_LN) {
        // bias + direct store from registers
#pragma unroll
        for (int i = 0; i < 4; ++i) {
            float v[CT];
#pragma unroll
            for (int j = 0; j < CP; ++j) unpack2(acc[i][j], v[2 * j], v[2 * j + 1]);
#pragma unroll
            for (int j = 0; j < CT; ++j)
                v[j] = __fadd_rn(v[j], __ldg(&bias[c0 + j]));
            long r = row0 + rg + 16 * i;
#pragma unroll
            for (int j = 0; j < CT; j += 4)
                *(float4*)&out[r * N + c0 + j] =
                    make_float4(v[j], v[j + 1], v[j + 2], v[j + 3]);
        }
        return;
    }

    // stage acc+bias to smem [64][NP] (reuses mainloop smem)
    float* S     = sm;
    float* meanv = sm + BM * NP;          // [64]
    float* rstdv = meanv + BM;            // [64]
#pragma unroll
    for (int i = 0; i < 4; ++i) {
        int r = rg + 16 * i;
        float v[CT];
#pragma unroll
        for (int j = 0; j < CP; ++j) unpack2(acc[i][j], v[2 * j], v[2 * j + 1]);
#pragma unroll
        for (int j = 0; j < CT; ++j)
            S[r * NP + c0 + j] = __fadd_rn(v[j], __ldg(&bias[c0 + j]));
    }
    __syncthreads();

    // Phase A: one thread per row, strict sequential left-fold (XLA:CPU).
    if (tid < BM) {
        const float* row = &S[tid * NP];
        float s = 0.0f;
        for (int j = 0; j < N; ++j) s = __fadd_rn(s, row[j]);
        float mean = __fdiv_rn(s, (float)N);   // /128, /256: exact
        float q = 0.0f;
        for (int j = 0; j < N; ++j) {
            float d = __fsub_rn(row[j], mean);
            q = __fadd_rn(q, __fmul_rn(d, d));
        }
        float var = __fdiv_rn(q, (float)N);
        float rstd = __fdiv_rn(1.0f, __fsqrt_rn(__fadd_rn(var, 1e-5f)));
        meanv[tid] = mean;
        rstdv[tid] = rstd;
    }
    __syncthreads();

    // Phase B: cooperative normalize + coalesced store. 4 threads per row.
    {
        const int r = tid >> 2, qq = tid & 3, cc0 = qq * (N / 4);
        float mean = meanv[r], rstd = rstdv[r];
#pragma unroll
        for (int j = 0; j < N / 4; j += 4) {
            float o[4];
#pragma unroll
            for (int e = 0; e < 4; ++e) {
                int c = cc0 + j + e;
                float v = S[r * NP + c];
                float t = __fmul_rn(__fsub_rn(v, mean), rstd);
                t = __fmul_rn(t, __ldg(&gamma[c]));
                o[e] = __fadd_rn(t, __ldg(&beta[c]));
            }
            *(float4*)&out[(row0 + r) * N + cc0 + j] = make_float4(o[0], o[1], o[2], o[3]);
        }
    }
}

// ---------------------------------------------------------------------------
// LIF scan over T (in-place: membrane input -> spikes). FEAT = 256.
// Exact: v = v + (x-v)*0.5, spike v>=1, hard reset 0. U=32 prefetch.
// ---------------------------------------------------------------------------
__global__ __launch_bounds__(64) void lif_spike_kernel(float* h)
{
    const int lane = blockIdx.x * blockDim.x + threadIdx.x;  // 0..B*HD-1
    const int b = lane >> 8;
    const int d = lane & 255;
    float* p = h + (long)b * TT * HDD + d;

    constexpr int U = 32;
    float cur[U];
#pragma unroll
    for (int u = 0; u < U; ++u) cur[u] = p[(long)u * HDD];

    float v = 0.0f;
    for (int t0 = 0; t0 < TT; t0 += U) {
        float nxt[U];
        if (t0 + U < TT) {
#pragma unroll
            for (int u = 0; u < U; ++u) nxt[u] = p[(long)(t0 + U + u) * HDD];
        }
#pragma unroll
        for (int u = 0; u < U; ++u) {
            float dd = __fsub_rn(cur[u], v);
            v = __fadd_rn(v, __fmul_rn(dd, 0.5f));
            float s = (v >= 1.0f) ? 1.0f : 0.0f;
            v = (v >= 1.0f) ? 0.0f : v;
            p[(long)(t0 + u) * HDD] = s;
        }
#pragma unroll
        for (int u = 0; u < U; ++u) cur[u] = nxt[u];
    }
}

// ---------------------------------------------------------------------------
// LIF scan + residual accumulate into x; write d_out at t = T-1. FEAT = 128.
// ---------------------------------------------------------------------------
__global__ __launch_bounds__(64) void lif_resid_kernel(const float* __restrict__ in,
                                                       float* x, float* dout)
{
    const int lane = blockIdx.x * blockDim.x + threadIdx.x;  // 0..B*D-1
    const int b = lane >> 7;
    const int d = lane & 127;
    const float* pi = in + (long)b * TT * DD + d;
    float*       px = x  + (long)b * TT * DD + d;

    constexpr int U = 32;
    float ci[U], cx[U];
#pragma unroll
    for (int u = 0; u < U; ++u) { ci[u] = pi[(long)u * DD]; cx[u] = px[(long)u * DD]; }

    float v = 0.0f;
    for (int t0 = 0; t0 < TT; t0 += U) {
        float ni[U], nx[U];
        if (t0 + U < TT) {
#pragma unroll
            for (int u = 0; u < U; ++u) {
                ni[u] = pi[(long)(t0 + U + u) * DD];
                nx[u] = px[(long)(t0 + U + u) * DD];
            }
        }
#pragma unroll
        for (int u = 0; u < U; ++u) {
            float dd = __fsub_rn(ci[u], v);
            v = __fadd_rn(v, __fmul_rn(dd, 0.5f));
            float s = (v >= 1.0f) ? 1.0f : 0.0f;
            v = (v >= 1.0f) ? 0.0f : v;
            float xv = __fadd_rn(cx[u], s);
            px[(long)(t0 + u) * DD] = xv;
            if (t0 + u == TT - 1) dout[b * DD + d] = xv;
        }
#pragma unroll
        for (int u = 0; u < U; ++u) { ci[u] = ni[u]; cx[u] = nx[u]; }
    }
}

// ---------------------------------------------------------------------------
// Launch
// ---------------------------------------------------------------------------
extern "C" void kernel_launch(void* const* d_in, const int* in_sizes, int n_in,
                              void* d_out, int out_size)
{
    const float* hist  = (const float*)d_in[0];
    const float* pw1   = (const float*)d_in[1];
    const float* pb1   = (const float*)d_in[2];
    const float* pw2   = (const float*)d_in[3];
    const float* pb2   = (const float*)d_in[4];
    const float* fc1_w = (const float*)d_in[5];
    const float* fc1_b = (const float*)d_in[6];
    const float* n1_g  = (const float*)d_in[7];
    const float* n1_b  = (const float*)d_in[8];
    const float* fc2_w = (const float*)d_in[9];
    const float* fc2_b = (const float*)d_in[10];
    const float* n2_g  = (const float*)d_in[11];
    const float* n2_b  = (const float*)d_in[12];
    float* out = (float*)d_out;

    float *px, *ph, *pt;
    cudaGetSymbolAddress((void**)&px, g_x);
    cudaGetSymbolAddress((void**)&ph, g_h);
    cudaGetSymbolAddress((void**)&pt, g_t);

    // dynamic smem: max(mainloop = As2 16896 + Bs 128*N, staging = (64*NP+128)*4)
    const int smem128 = 64 * (32 + 1) * 8 + 32 * 128 * 4;        // 33280
    const int smem128s = (64 * 129 + 128) * 4;                   // 33536
    const int sA = (smem128 > smem128s) ? smem128 : smem128s;    // 33536
    const int smem256 = (64 * 257 + 128) * 4;                    // 66304 (> mainloop 49664)
    cudaFuncSetAttribute(gemm_ln_f2<DD, H0, false>,
                         cudaFuncAttributeMaxDynamicSharedMemorySize, sA);
    cudaFuncSetAttribute(gemm_ln_f2<HDD, DD, true>,
                         cudaFuncAttributeMaxDynamicSharedMemorySize, smem256);
    cudaFuncSetAttribute(gemm_ln_f2<DD, HDD, true>,
                         cudaFuncAttributeMaxDynamicSharedMemorySize, sA);

    // Projector: hist@pw1 -> gelu -> @pw2 (+biases) -> g_x
    proj1_kernel<<<(MM * H0) / 256, 256>>>(hist, pw1, pb1, pt);
    gemm_ln_f2<DD, H0, false><<<MM / 64, 256, sA>>>(pt, pw2, pb2, nullptr, nullptr, px);

    for (int i = 0; i < DEPTH; ++i) {
        gemm_ln_f2<HDD, DD, true><<<MM / 64, 256, smem256>>>(
            px, fc1_w + (long)i * DD * HDD, fc1_b + i * HDD,
            n1_g + i * HDD, n1_b + i * HDD, ph);
        lif_spike_kernel<<<(BB * HDD) / 64, 64>>>(ph);
        gemm_ln_f2<DD, HDD, true><<<MM / 64, 256, sA>>>(
            ph, fc2_w + (long)i * HDD * DD, fc2_b + i * DD,
            n2_g + i * DD, n2_b + i * DD, pt);
        lif_resid_kernel<<<(BB * DD) / 64, 64>>>(pt, px, out);
    }
}

// round 15
// speedup vs baseline: 1.1882x; 1.0394x over previous
#include <cuda_runtime.h>
#include <math.h>
#include <stdint.h>

// Problem constants
#define BB    64
#define TT    2048
#define NIN   4
#define H0    64
#define DD    128
#define HDD   256
#define DEPTH 4
#define MM    (BB * TT)   // 131072 rows

// Scratch (device globals; allocation-free per harness rules)
__device__ float g_x[(size_t)MM * DD];    // 64 MB  running features [B,T,D]
__device__ float g_h[(size_t)MM * HDD];   // 128 MB hidden / spikes   [B,T,HD]
__device__ float g_t[(size_t)MM * DD];    // 64 MB  temp              [B,T,D]

// ---------------------------------------------------------------------------
// Packed f32x2 helpers (sm_103a). Each lane is an independent, correctly
// rounded fp32 op — bit-identical to scalar fmaf per output.
// ---------------------------------------------------------------------------
__device__ __forceinline__ unsigned long long pack_dup(float a) {
    unsigned long long r;
    asm("mov.b64 %0, {%1, %1};" : "=l"(r) : "f"(a));
    return r;
}
__device__ __forceinline__ void unpack2(unsigned long long v, float& lo, float& hi) {
    asm("mov.b64 {%0, %1}, %2;" : "=f"(lo), "=f"(hi) : "l"(v));
}
#define FFMA2(acc, a2, b2) \
    asm("fma.rn.f32x2 %0, %1, %2, %0;" : "+l"(acc) : "l"(a2), "l"(b2))

// ---------------------------------------------------------------------------
// XLA erf f32 (rational poly, clamp +-4, unfused mul/add, rounded divide)
// ---------------------------------------------------------------------------
__device__ __forceinline__ float xla_erf(float x) {
    x = fminf(fmaxf(x, -4.0f), 4.0f);
    float x2 = __fmul_rn(x, x);
    float p = -2.72614225801306e-10f;
    p = __fadd_rn(__fmul_rn(p, x2),  2.77068142495902e-08f);
    p = __fadd_rn(__fmul_rn(p, x2), -2.10102402082508e-06f);
    p = __fadd_rn(__fmul_rn(p, x2), -5.69250639462346e-05f);
    p = __fadd_rn(__fmul_rn(p, x2), -7.34990630326855e-04f);
    p = __fadd_rn(__fmul_rn(p, x2), -2.95459980854025e-03f);
    p = __fadd_rn(__fmul_rn(p, x2), -1.60960333262415e-02f);
    p = __fmul_rn(x, p);
    float q = -1.45660718464996e-05f;
    q = __fadd_rn(__fmul_rn(q, x2), -2.13374055278905e-04f);
    q = __fadd_rn(__fmul_rn(q, x2), -1.68282697438203e-03f);
    q = __fadd_rn(__fmul_rn(q, x2), -7.37332916720468e-03f);
    q = __fadd_rn(__fmul_rn(q, x2), -1.42647390514189e-02f);
    return __fdiv_rn(p, q);
}

__device__ __forceinline__ float gelu_exact(float x) {
    float u = __fdiv_rn(x, 1.4142135623730951f);
    float e = xla_erf(u);
    return __fmul_rn(__fmul_rn(x, __fadd_rn(e, 1.0f)), 0.5f);
}

// ---------------------------------------------------------------------------
// Projector stage 1: g1[r,j] = gelu(hist[r,:4] @ pw1[:,j] + pb1[j])
// ---------------------------------------------------------------------------
__global__ void proj1_kernel(const float* __restrict__ hist,
                             const float* __restrict__ pw1,
                             const float* __restrict__ pb1,
                             float* __restrict__ g1)
{
    long idx = (long)blockIdx.x * blockDim.x + threadIdx.x;  // M*64 total
    long r = idx >> 6;
    int  j = (int)(idx & 63);
    const float* hp = hist + r * NIN;
    float acc = 0.0f;
    acc = fmaf(__ldg(hp + 0), __ldg(&pw1[0 * H0 + j]), acc);
    acc = fmaf(__ldg(hp + 1), __ldg(&pw1[1 * H0 + j]), acc);
    acc = fmaf(__ldg(hp + 2), __ldg(&pw1[2 * H0 + j]), acc);
    acc = fmaf(__ldg(hp + 3), __ldg(&pw1[3 * H0 + j]), acc);
    float h = __fadd_rn(acc, __ldg(&pb1[j]));
    g1[idx] = gelu_exact(h);
}

// ---------------------------------------------------------------------------
// Fused GEMM (+bias) (+LayerNorm): FFMA2 mainloop + CPU-exact epilogue.
//  - per-output: single ascending-k fp32 FMA chain (bit-identical to R7/R9)
//  - LN: strict sequential left-fold per row (one thread), rstd = 1/sqrt
// CTA: 64 rows x N cols, 256 threads = 8 warps.
// Warp owns rows warp*8..+7 (R9 mapping). Lane owns CP=N/64 column-PAIRS:
// pair j = cols {64j+2*lane, 64j+2*lane+1}.
//  - A pre-duplicated {a,a} in smem; per-row load is a warp-uniform
//    broadcast LDS.64 (conflict-free, no mov.b64 packs).
//  - B pair loads: LDS.64 at word offset 2*lane -> 16-lane phase covers
//    banks 0..31 exactly once (conflict-free).
// ---------------------------------------------------------------------------
template<int N, int K, bool DO_LN>
__global__ __launch_bounds__(256, 2)
void gemm_ln_f2(const float* __restrict__ A, const float* __restrict__ W,
                const float* __restrict__ bias,
                const float* __restrict__ gamma, const float* __restrict__ beta,
                float* __restrict__ out)
{
    constexpr int BM = 64, BK = 32;
    constexpr int CP = N / 64;       // packed col-pairs per lane (4 or 2)
    constexpr int NP = N + 1;
    constexpr int ASTR = BK + 1;     // A row stride in ull units (33)
    extern __shared__ float sm[];
    unsigned long long* As2 = (unsigned long long*)sm;   // [64][33] packed {a,a}
    float* Bs = sm + BM * ASTR * 2;                      // [32][N]

    const int tid = threadIdx.x;
    const int lane = tid & 31, warp = tid >> 5;
    const long row0 = (long)blockIdx.x * BM;

    unsigned long long acc[8][CP];
#pragma unroll
    for (int i = 0; i < 8; ++i)
#pragma unroll
        for (int j = 0; j < CP; ++j) acc[i][j] = 0ull;

    for (int kk = 0; kk < K; kk += BK) {
        // A tile 64x32, stored duplicated {a,a}
#pragma unroll
        for (int it = 0; it < 2; ++it) {
            int e4 = tid + it * 256;
            int r  = e4 >> 3;
            int k4 = (e4 & 7) << 2;
            float4 v = *(const float4*)&A[(row0 + r) * K + kk + k4];
            unsigned long long* d = &As2[r * ASTR + k4];
            d[0] = pack_dup(v.x); d[1] = pack_dup(v.y);
            d[2] = pack_dup(v.z); d[3] = pack_dup(v.w);
        }
        // B tile 32xN
        constexpr int B4 = BK * N / 4;
#pragma unroll
        for (int it = 0; it < B4 / 256; ++it) {
            int e4 = tid + it * 256;
            int kb = e4 / (N / 4);
            int c4 = (e4 % (N / 4)) << 2;
            *(float4*)&Bs[kb * N + c4] = *(const float4*)&W[(long)(kk + kb) * N + c4];
        }
        __syncthreads();
#pragma unroll
        for (int k = 0; k < BK; ++k) {
            unsigned long long b2[CP];
#pragma unroll
            for (int j = 0; j < CP; ++j)
                b2[j] = *(const unsigned long long*)&Bs[k * N + 64 * j + 2 * lane];
#pragma unroll
            for (int i = 0; i < 8; ++i) {
                unsigned long long a2 = As2[(warp * 8 + i) * ASTR + k];  // broadcast
#pragma unroll
                for (int j = 0; j < CP; ++j) FFMA2(acc[i][j], a2, b2[j]);
            }
        }
        __syncthreads();
    }

    if (!DO_LN) {
        // bias + direct pair stores (coalesced: lanes cover 64 contiguous cols)
#pragma unroll
        for (int i = 0; i < 8; ++i) {
            long r = row0 + warp * 8 + i;
#pragma unroll
            for (int j = 0; j < CP; ++j) {
                float v0, v1; unpack2(acc[i][j], v0, v1);
                int c = 64 * j + 2 * lane;
                v0 = __fadd_rn(v0, __ldg(&bias[c]));
                v1 = __fadd_rn(v1, __ldg(&bias[c + 1]));
                *(float2*)&out[r * N + c] = make_float2(v0, v1);
            }
        }
        return;
    }

    // stage acc+bias to smem [64][NP] (reuses mainloop smem)
    float* S     = sm;
    float* meanv = sm + BM * NP;          // [64]
    float* rstdv = meanv + BM;            // [64]
#pragma unroll
    for (int i = 0; i < 8; ++i) {
        int r = warp * 8 + i;
#pragma unroll
        for (int j = 0; j < CP; ++j) {
            float v0, v1; unpack2(acc[i][j], v0, v1);
            int c = 64 * j + 2 * lane;
            S[r * NP + c]     = __fadd_rn(v0, __ldg(&bias[c]));
            S[r * NP + c + 1] = __fadd_rn(v1, __ldg(&bias[c + 1]));
        }
    }
    __syncthreads();

    // Phase A: one thread per row, strict sequential left-fold (XLA:CPU).
    if (tid < BM) {
        const float* row = &S[tid * NP];
        float s = 0.0f;
        for (int j = 0; j < N; ++j) s = __fadd_rn(s, row[j]);
        float mean = __fdiv_rn(s, (float)N);   // /128, /256: exact
        float q = 0.0f;
        for (int j = 0; j < N; ++j) {
            float d = __fsub_rn(row[j], mean);
            q = __fadd_rn(q, __fmul_rn(d, d));
        }
        float var = __fdiv_rn(q, (float)N);
        float rstd = __fdiv_rn(1.0f, __fsqrt_rn(__fadd_rn(var, 1e-5f)));
        meanv[tid] = mean;
        rstdv[tid] = rstd;
    }
    __syncthreads();

    // Phase B: cooperative normalize + coalesced store. 4 threads per row.
    {
        const int r = tid >> 2, qq = tid & 3, cc0 = qq * (N / 4);
        float mean = meanv[r], rstd = rstdv[r];
#pragma unroll
        for (int j = 0; j < N / 4; j += 4) {
            float o[4];
#pragma unroll
            for (int e = 0; e < 4; ++e) {
                int c = cc0 + j + e;
                float v = S[r * NP + c];
                float t = __fmul_rn(__fsub_rn(v, mean), rstd);
                t = __fmul_rn(t, __ldg(&gamma[c]));
                o[e] = __fadd_rn(t, __ldg(&beta[c]));
            }
            *(float4*)&out[(row0 + r) * N + cc0 + j] = make_float4(o[0], o[1], o[2], o[3]);
        }
    }
}

// ---------------------------------------------------------------------------
// LIF scan over T (in-place: membrane input -> spikes). FEAT = 256.
// Exact: v = v + (x-v)*0.5, spike v>=1, hard reset 0. U=32 prefetch.
// ---------------------------------------------------------------------------
__global__ __launch_bounds__(64) void lif_spike_kernel(float* h)
{
    const int lane = blockIdx.x * blockDim.x + threadIdx.x;  // 0..B*HD-1
    const int b = lane >> 8;
    const int d = lane & 255;
    float* p = h + (long)b * TT * HDD + d;

    constexpr int U = 32;
    float cur[U];
#pragma unroll
    for (int u = 0; u < U; ++u) cur[u] = p[(long)u * HDD];

    float v = 0.0f;
    for (int t0 = 0; t0 < TT; t0 += U) {
        float nxt[U];
        if (t0 + U < TT) {
#pragma unroll
            for (int u = 0; u < U; ++u) nxt[u] = p[(long)(t0 + U + u) * HDD];
        }
#pragma unroll
        for (int u = 0; u < U; ++u) {
            float dd = __fsub_rn(cur[u], v);
            v = __fadd_rn(v, __fmul_rn(dd, 0.5f));
            float s = (v >= 1.0f) ? 1.0f : 0.0f;
            v = (v >= 1.0f) ? 0.0f : v;
            p[(long)(t0 + u) * HDD] = s;
        }
#pragma unroll
        for (int u = 0; u < U; ++u) cur[u] = nxt[u];
    }
}

// ---------------------------------------------------------------------------
// LIF scan + residual accumulate into x; write d_out at t = T-1. FEAT = 128.
// ---------------------------------------------------------------------------
__global__ __launch_bounds__(64) void lif_resid_kernel(const float* __restrict__ in,
                                                       float* x, float* dout)
{
    const int lane = blockIdx.x * blockDim.x + threadIdx.x;  // 0..B*D-1
    const int b = lane >> 7;
    const int d = lane & 127;
    const float* pi = in + (long)b * TT * DD + d;
    float*       px = x  + (long)b * TT * DD + d;

    constexpr int U = 32;
    float ci[U], cx[U];
#pragma unroll
    for (int u = 0; u < U; ++u) { ci[u] = pi[(long)u * DD]; cx[u] = px[(long)u * DD]; }

    float v = 0.0f;
    for (int t0 = 0; t0 < TT; t0 += U) {
        float ni[U], nx[U];
        if (t0 + U < TT) {
#pragma unroll
            for (int u = 0; u < U; ++u) {
                ni[u] = pi[(long)(t0 + U + u) * DD];
                nx[u] = px[(long)(t0 + U + u) * DD];
            }
        }
#pragma unroll
        for (int u = 0; u < U; ++u) {
            float dd = __fsub_rn(ci[u], v);
            v = __fadd_rn(v, __fmul_rn(dd, 0.5f));
            float s = (v >= 1.0f) ? 1.0f : 0.0f;
            v = (v >= 1.0f) ? 0.0f : v;
            float xv = __fadd_rn(cx[u], s);
            px[(long)(t0 + u) * DD] = xv;
            if (t0 + u == TT - 1) dout[b * DD + d] = xv;
        }
#pragma unroll
        for (int u = 0; u < U; ++u) { ci[u] = ni[u]; cx[u] = nx[u]; }
    }
}

// ---------------------------------------------------------------------------
// Launch
// ---------------------------------------------------------------------------
extern "C" void kernel_launch(void* const* d_in, const int* in_sizes, int n_in,
                              void* d_out, int out_size)
{
    const float* hist  = (const float*)d_in[0];
    const float* pw1   = (const float*)d_in[1];
    const float* pb1   = (const float*)d_in[2];
    const float* pw2   = (const float*)d_in[3];
    const float* pb2   = (const float*)d_in[4];
    const float* fc1_w = (const float*)d_in[5];
    const float* fc1_b = (const float*)d_in[6];
    const float* n1_g  = (const float*)d_in[7];
    const float* n1_b  = (const float*)d_in[8];
    const float* fc2_w = (const float*)d_in[9];
    const float* fc2_b = (const float*)d_in[10];
    const float* n2_g  = (const float*)d_in[11];
    const float* n2_b  = (const float*)d_in[12];
    float* out = (float*)d_out;

    float *px, *ph, *pt;
    cudaGetSymbolAddress((void**)&px, g_x);
    cudaGetSymbolAddress((void**)&ph, g_h);
    cudaGetSymbolAddress((void**)&pt, g_t);

    // dynamic smem: max(mainloop = As2 16896 + Bs 128*N, staging = (64*NP+128)*4)
    const int smem128 = 64 * (32 + 1) * 8 + 32 * 128 * 4;        // 33280
    const int smem128s = (64 * 129 + 128) * 4;                   // 33536
    const int sA = (smem128 > smem128s) ? smem128 : smem128s;    // 33536
    const int smem256 = (64 * 257 + 128) * 4;                    // 66304 (> mainloop 49664)
    cudaFuncSetAttribute(gemm_ln_f2<DD, H0, false>,
                         cudaFuncAttributeMaxDynamicSharedMemorySize, sA);
    cudaFuncSetAttribute(gemm_ln_f2<HDD, DD, true>,
                         cudaFuncAttributeMaxDynamicSharedMemorySize, smem256);
    cudaFuncSetAttribute(gemm_ln_f2<DD, HDD, true>,
                         cudaFuncAttributeMaxDynamicSharedMemorySize, sA);

    // Projector: hist@pw1 -> gelu -> @pw2 (+biases) -> g_x
    proj1_kernel<<<(MM * H0) / 256, 256>>>(hist, pw1, pb1, pt);
    gemm_ln_f2<DD, H0, false><<<MM / 64, 256, sA>>>(pt, pw2, pb2, nullptr, nullptr, px);

    for (int i = 0; i < DEPTH; ++i) {
        gemm_ln_f2<HDD, DD, true><<<MM / 64, 256, smem256>>>(
            px, fc1_w + (long)i * DD * HDD, fc1_b + i * HDD,
            n1_g + i * HDD, n1_b + i * HDD, ph);
        lif_spike_kernel<<<(BB * HDD) / 64, 64>>>(ph);
        gemm_ln_f2<DD, HDD, true><<<MM / 64, 256, sA>>>(
            ph, fc2_w + (long)i * HDD * DD, fc2_b + i * DD,
            n2_g + i * DD, n2_b + i * DD, pt);
        lif_resid_kernel<<<(BB * DD) / 64, 64>>>(pt, px, out);
    }
}

// round 17
// speedup vs baseline: 1.5111x; 1.2718x over previous
#include <cuda_runtime.h>
#include <math.h>
#include <stdint.h>

// Problem constants
#define BB    64
#define TT    2048
#define NIN   4
#define H0    64
#define DD    128
#define HDD   256
#define DEPTH 4
#define MM    (BB * TT)   // 131072 rows

// Scratch (device globals; allocation-free per harness rules)
__device__ float    g_x[(size_t)MM * DD];    // 64 MB  running features [B,T,D]
__device__ float    g_h[(size_t)MM * HDD];   // 128 MB fc1 output (membrane input)
__device__ float    g_t[(size_t)MM * DD];    // 64 MB  temp (fc2 out)
__device__ uint32_t g_m[(size_t)MM * 8];     // 4 MB   spike bitmask [row][k/32]

// ---------------------------------------------------------------------------
// Packed f32x2 helpers (sm_103a). Each lane is an independent, correctly
// rounded fp32 op — bit-identical to scalar fmaf/fadd per output.
// ---------------------------------------------------------------------------
__device__ __forceinline__ unsigned long long pack_dup(float a) {
    unsigned long long r;
    asm("mov.b64 %0, {%1, %1};" : "=l"(r) : "f"(a));
    return r;
}
__device__ __forceinline__ void unpack2(unsigned long long v, float& lo, float& hi) {
    asm("mov.b64 {%0, %1}, %2;" : "=f"(lo), "=f"(hi) : "l"(v));
}
#define FFMA2(acc, a2, b2) \
    asm("fma.rn.f32x2 %0, %1, %2, %0;" : "+l"(acc) : "l"(a2), "l"(b2))
#define FADD2(acc, b2) \
    asm("add.rn.f32x2 %0, %0, %1;" : "+l"(acc) : "l"(b2))

// ---------------------------------------------------------------------------
// XLA erf f32 (rational poly, clamp +-4, unfused mul/add, rounded divide)
// ---------------------------------------------------------------------------
__device__ __forceinline__ float xla_erf(float x) {
    x = fminf(fmaxf(x, -4.0f), 4.0f);
    float x2 = __fmul_rn(x, x);
    float p = -2.72614225801306e-10f;
    p = __fadd_rn(__fmul_rn(p, x2),  2.77068142495902e-08f);
    p = __fadd_rn(__fmul_rn(p, x2), -2.10102402082508e-06f);
    p = __fadd_rn(__fmul_rn(p, x2), -5.69250639462346e-05f);
    p = __fadd_rn(__fmul_rn(p, x2), -7.34990630326855e-04f);
    p = __fadd_rn(__fmul_rn(p, x2), -2.95459980854025e-03f);
    p = __fadd_rn(__fmul_rn(p, x2), -1.60960333262415e-02f);
    p = __fmul_rn(x, p);
    float q = -1.45660718464996e-05f;
    q = __fadd_rn(__fmul_rn(q, x2), -2.13374055278905e-04f);
    q = __fadd_rn(__fmul_rn(q, x2), -1.68282697438203e-03f);
    q = __fadd_rn(__fmul_rn(q, x2), -7.37332916720468e-03f);
    q = __fadd_rn(__fmul_rn(q, x2), -1.42647390514189e-02f);
    return __fdiv_rn(p, q);
}

__device__ __forceinline__ float gelu_exact(float x) {
    float u = __fdiv_rn(x, 1.4142135623730951f);
    float e = xla_erf(u);
    return __fmul_rn(__fmul_rn(x, __fadd_rn(e, 1.0f)), 0.5f);
}

// ---------------------------------------------------------------------------
// Projector stage 1: g1[r,j] = gelu(hist[r,:4] @ pw1[:,j] + pb1[j])
// ---------------------------------------------------------------------------
__global__ void proj1_kernel(const float* __restrict__ hist,
                             const float* __restrict__ pw1,
                             const float* __restrict__ pb1,
                             float* __restrict__ g1)
{
    long idx = (long)blockIdx.x * blockDim.x + threadIdx.x;  // M*64 total
    long r = idx >> 6;
    int  j = (int)(idx & 63);
    const float* hp = hist + r * NIN;
    float acc = 0.0f;
    acc = fmaf(__ldg(hp + 0), __ldg(&pw1[0 * H0 + j]), acc);
    acc = fmaf(__ldg(hp + 1), __ldg(&pw1[1 * H0 + j]), acc);
    acc = fmaf(__ldg(hp + 2), __ldg(&pw1[2 * H0 + j]), acc);
    acc = fmaf(__ldg(hp + 3), __ldg(&pw1[3 * H0 + j]), acc);
    float h = __fadd_rn(acc, __ldg(&pb1[j]));
    g1[idx] = gelu_exact(h);
}

// ---------------------------------------------------------------------------
// Dense GEMM (+bias) (+LayerNorm): R9 layout (best measured), verbatim.
// Warp owns rows warp*8..+7; lane owns CT=N/32 contiguous cols.
// Sequential-left-fold LN epilogue (CPU-exact), rstd = 1/sqrt.
// ---------------------------------------------------------------------------
template<int N, int K, bool DO_LN>
__global__ __launch_bounds__(256, 2)
void gemm_ln_f2(const float* __restrict__ A, const float* __restrict__ W,
                const float* __restrict__ bias,
                const float* __restrict__ gamma, const float* __restrict__ beta,
                float* __restrict__ out)
{
    constexpr int BM = 64, BK = 32;
    constexpr int CT = N / 32;       // cols per lane (8 or 4)
    constexpr int CP = CT / 2;       // packed col-pairs (4 or 2)
    constexpr int NP = N + 1;
    extern __shared__ float sm[];
    float (*As)[BK + 1] = (float (*)[BK + 1])sm;       // [64][33]
    float* Bs = sm + BM * (BK + 1);                    // [32][N]

    const int tid = threadIdx.x;
    const int lane = tid & 31, warp = tid >> 5;
    const long row0 = (long)blockIdx.x * BM;

    unsigned long long acc[8][CP];
#pragma unroll
    for (int i = 0; i < 8; ++i)
#pragma unroll
        for (int j = 0; j < CP; ++j) acc[i][j] = 0ull;

    for (int kk = 0; kk < K; kk += BK) {
#pragma unroll
        for (int it = 0; it < 2; ++it) {
            int e4 = tid + it * 256;
            int r  = e4 >> 3;
            int k4 = (e4 & 7) << 2;
            float4 v = *(const float4*)&A[(row0 + r) * K + kk + k4];
            As[r][k4 + 0] = v.x; As[r][k4 + 1] = v.y;
            As[r][k4 + 2] = v.z; As[r][k4 + 3] = v.w;
        }
        constexpr int B4 = BK * N / 4;
#pragma unroll
        for (int it = 0; it < B4 / 256; ++it) {
            int e4 = tid + it * 256;
            int kb = e4 / (N / 4);
            int c4 = (e4 % (N / 4)) << 2;
            *(float4*)&Bs[kb * N + c4] = *(const float4*)&W[(long)(kk + kb) * N + c4];
        }
        __syncthreads();
#pragma unroll
        for (int k = 0; k < BK; ++k) {
            unsigned long long b2[CP];
            if (CT == 8) {
                ulonglong2 p0 = *(const ulonglong2*)&Bs[k * N + lane * 8];
                ulonglong2 p1 = *(const ulonglong2*)&Bs[k * N + lane * 8 + 4];
                b2[0] = p0.x; b2[1] = p0.y; b2[2] = p1.x; b2[3] = p1.y;
            } else {
                ulonglong2 p0 = *(const ulonglong2*)&Bs[k * N + lane * 4];
                b2[0] = p0.x; b2[1] = p0.y;
            }
#pragma unroll
            for (int i = 0; i < 8; ++i) {
                unsigned long long a2 = pack_dup(As[warp * 8 + i][k]);
#pragma unroll
                for (int j = 0; j < CP; ++j) FFMA2(acc[i][j], a2, b2[j]);
            }
        }
        __syncthreads();
    }

    const int c0 = lane * CT;

    if (!DO_LN) {
#pragma unroll
        for (int i = 0; i < 8; ++i) {
            float v[CT];
#pragma unroll
            for (int j = 0; j < CP; ++j) unpack2(acc[i][j], v[2 * j], v[2 * j + 1]);
#pragma unroll
            for (int j = 0; j < CT; ++j)
                v[j] = __fadd_rn(v[j], __ldg(&bias[c0 + j]));
            long r = row0 + warp * 8 + i;
#pragma unroll
            for (int j = 0; j < CT; j += 4)
                *(float4*)&out[r * N + c0 + j] =
                    make_float4(v[j], v[j + 1], v[j + 2], v[j + 3]);
        }
        return;
    }

    float* S     = sm;
    float* meanv = sm + BM * NP;          // [64]
    float* rstdv = meanv + BM;            // [64]
#pragma unroll
    for (int i = 0; i < 8; ++i) {
        int r = warp * 8 + i;
        float v[CT];
#pragma unroll
        for (int j = 0; j < CP; ++j) unpack2(acc[i][j], v[2 * j], v[2 * j + 1]);
#pragma unroll
        for (int j = 0; j < CT; ++j)
            S[r * NP + c0 + j] = __fadd_rn(v[j], __ldg(&bias[c0 + j]));
    }
    __syncthreads();

    if (tid < BM) {
        const float* row = &S[tid * NP];
        float s = 0.0f;
        for (int j = 0; j < N; ++j) s = __fadd_rn(s, row[j]);
        float mean = __fdiv_rn(s, (float)N);
        float q = 0.0f;
        for (int j = 0; j < N; ++j) {
            float d = __fsub_rn(row[j], mean);
            q = __fadd_rn(q, __fmul_rn(d, d));
        }
        float var = __fdiv_rn(q, (float)N);
        float rstd = __fdiv_rn(1.0f, __fsqrt_rn(__fadd_rn(var, 1e-5f)));
        meanv[tid] = mean;
        rstdv[tid] = rstd;
    }
    __syncthreads();

    {
        const int r = tid >> 2, qq = tid & 3, cc0 = qq * (N / 4);
        float mean = meanv[r], rstd = rstdv[r];
#pragma unroll
        for (int j = 0; j < N / 4; j += 4) {
            float o[4];
#pragma unroll
            for (int e = 0; e < 4; ++e) {
                int c = cc0 + j + e;
                float v = S[r * NP + c];
                float t = __fmul_rn(__fsub_rn(v, mean), rstd);
                t = __fmul_rn(t, __ldg(&gamma[c]));
                o[e] = __fadd_rn(t, __ldg(&beta[c]));
            }
            *(float4*)&out[(row0 + r) * N + cc0 + j] = make_float4(o[0], o[1], o[2], o[3]);
        }
    }
}

// ---------------------------------------------------------------------------
// SPARSE fc2 GEMM + bias + LN: A is binary spikes given as bitmask.
// out[r,c] = LN( sum_{k: mask bit set, ascending} W[k,c] + bias[c] )
// Bit-exact to dense chain: fmaf(0,w,acc)=acc, fmaf(1,w,acc)=fadd(acc,w).
// N=128, K=256. CTA 64 rows x 128 cols, 256 threads = 8 warps.
// Warp owns rows warp*8..+7; lane owns col pairs {2*lane, 64+2*lane}.
// Mask word per (row, 32-k chunk); warp-uniform while(m) loop, no divergence.
// ---------------------------------------------------------------------------
__global__ __launch_bounds__(256, 2)
void gemm_sparse_ln(const uint32_t* __restrict__ mask,
                    const float* __restrict__ W,
                    const float* __restrict__ bias,
                    const float* __restrict__ gamma, const float* __restrict__ beta,
                    float* __restrict__ out)
{
    constexpr int BM = 64, BK = 32, N = 128, K = 256, NP = N + 1, CP = 2;
    extern __shared__ float sm[];
    float* Bs = sm;                       // [32][128]

    const int tid = threadIdx.x;
    const int lane = tid & 31, warp = tid >> 5;
    const long row0 = (long)blockIdx.x * BM;
    const unsigned FULL = 0xffffffffu;

    unsigned long long acc[8][CP];
#pragma unroll
    for (int i = 0; i < 8; ++i) { acc[i][0] = 0ull; acc[i][1] = 0ull; }

    for (int kk = 0; kk < K; kk += BK) {
        // mask words for this warp's 8 rows (lanes 0..7 load)
        uint32_t mw = 0;
        if (lane < 8)
            mw = __ldg(&mask[(row0 + warp * 8 + lane) * 8 + (kk >> 5)]);
        // B tile 32x128
#pragma unroll
        for (int it = 0; it < 4; ++it) {
            int e4 = tid + it * 256;
            int kb = e4 >> 5;
            int c4 = (e4 & 31) << 2;
            *(float4*)&Bs[kb * N + c4] = *(const float4*)&W[(long)(kk + kb) * N + c4];
        }
        __syncthreads();
#pragma unroll
        for (int i = 0; i < 8; ++i) {
            uint32_t m = __shfl_sync(FULL, mw, i);
            while (m) {
                int k = __ffs(m) - 1;
                m &= m - 1;
                unsigned long long b0 = *(const unsigned long long*)&Bs[k * N + 2 * lane];
                unsigned long long b1 = *(const unsigned long long*)&Bs[k * N + 64 + 2 * lane];
                FADD2(acc[i][0], b0);
                FADD2(acc[i][1], b1);
            }
        }
        __syncthreads();
    }

    // stage acc+bias to smem [64][NP]
    float* S     = sm;
    float* meanv = sm + BM * NP;
    float* rstdv = meanv + BM;
#pragma unroll
    for (int i = 0; i < 8; ++i) {
        int r = warp * 8 + i;
#pragma unroll
        for (int j = 0; j < CP; ++j) {
            float v0, v1; unpack2(acc[i][j], v0, v1);
            int c = 64 * j + 2 * lane;
            S[r * NP + c]     = __fadd_rn(v0, __ldg(&bias[c]));
            S[r * NP + c + 1] = __fadd_rn(v1, __ldg(&bias[c + 1]));
        }
    }
    __syncthreads();

    // Phase A: strict sequential left-fold per row (XLA:CPU exact)
    if (tid < BM) {
        const float* row = &S[tid * NP];
        float s = 0.0f;
        for (int j = 0; j < N; ++j) s = __fadd_rn(s, row[j]);
        float mean = __fdiv_rn(s, (float)N);
        float q = 0.0f;
        for (int j = 0; j < N; ++j) {
            float d = __fsub_rn(row[j], mean);
            q = __fadd_rn(q, __fmul_rn(d, d));
        }
        float var = __fdiv_rn(q, (float)N);
        float rstd = __fdiv_rn(1.0f, __fsqrt_rn(__fadd_rn(var, 1e-5f)));
        meanv[tid] = mean;
        rstdv[tid] = rstd;
    }
    __syncthreads();

    // Phase B: cooperative normalize + coalesced store
    {
        const int r = tid >> 2, qq = tid & 3, cc0 = qq * (N / 4);
        float mean = meanv[r], rstd = rstdv[r];
#pragma unroll
        for (int j = 0; j < N / 4; j += 4) {
            float o[4];
#pragma unroll
            for (int e = 0; e < 4; ++e) {
                int c = cc0 + j + e;
                float v = S[r * NP + c];
                float t = __fmul_rn(__fsub_rn(v, mean), rstd);
                t = __fmul_rn(t, __ldg(&gamma[c]));
                o[e] = __fadd_rn(t, __ldg(&beta[c]));
            }
            *(float4*)&out[(row0 + r) * N + cc0 + j] = make_float4(o[0], o[1], o[2], o[3]);
        }
    }
}

// ---------------------------------------------------------------------------
// LIF scan over T: membrane input -> spike BITMASK (no float spike writes).
// Exact: v = v + (x-v)*0.5, spike v>=1, hard reset 0. U=32 prefetch.
// Warp = 32 consecutive d of same b -> ballot = mask word (d>>5) of row (b,t).
// ---------------------------------------------------------------------------
__global__ __launch_bounds__(64) void lif_spike_kernel(const float* __restrict__ h,
                                                       uint32_t* __restrict__ mask)
{
    const int lane = blockIdx.x * blockDim.x + threadIdx.x;  // 0..B*HD-1
    const int b = lane >> 8;
    const int d = lane & 255;
    const float* p = h + (long)b * TT * HDD + d;
    const int w32 = d >> 5;
    const bool lead = ((threadIdx.x & 31) == 0);
    uint32_t* mrow = mask + (long)b * TT * 8 + w32;
    const unsigned FULL = 0xffffffffu;

    constexpr int U = 32;
    float cur[U];
#pragma unroll
    for (int u = 0; u < U; ++u) cur[u] = p[(long)u * HDD];

    float v = 0.0f;
    for (int t0 = 0; t0 < TT; t0 += U) {
        float nxt[U];
        if (t0 + U < TT) {
#pragma unroll
            for (int u = 0; u < U; ++u) nxt[u] = p[(long)(t0 + U + u) * HDD];
        }
#pragma unroll
        for (int u = 0; u < U; ++u) {
            float dd = __fsub_rn(cur[u], v);
            v = __fadd_rn(v, __fmul_rn(dd, 0.5f));
            bool fire = (v >= 1.0f);
            uint32_t bal = __ballot_sync(FULL, fire);
            if (fire) v = 0.0f;
            if (lead) mrow[(long)(t0 + u) * 8] = bal;
        }
#pragma unroll
        for (int u = 0; u < U; ++u) cur[u] = nxt[u];
    }
}

// ---------------------------------------------------------------------------
// LIF scan + residual accumulate into x; write d_out at t = T-1. FEAT = 128.
// ---------------------------------------------------------------------------
__global__ __launch_bounds__(64) void lif_resid_kernel(const float* __restrict__ in,
                                                       float* x, float* dout)
{
    const int lane = blockIdx.x * blockDim.x + threadIdx.x;  // 0..B*D-1
    const int b = lane >> 7;
    const int d = lane & 127;
    const float* pi = in + (long)b * TT * DD + d;
    float*       px = x  + (long)b * TT * DD + d;

    constexpr int U = 32;
    float ci[U], cx[U];
#pragma unroll
    for (int u = 0; u < U; ++u) { ci[u] = pi[(long)u * DD]; cx[u] = px[(long)u * DD]; }

    float v = 0.0f;
    for (int t0 = 0; t0 < TT; t0 += U) {
        float ni[U], nx[U];
        if (t0 + U < TT) {
#pragma unroll
            for (int u = 0; u < U; ++u) {
                ni[u] = pi[(long)(t0 + U + u) * DD];
                nx[u] = px[(long)(t0 + U + u) * DD];
            }
        }
#pragma unroll
        for (int u = 0; u < U; ++u) {
            float dd = __fsub_rn(ci[u], v);
            v = __fadd_rn(v, __fmul_rn(dd, 0.5f));
            float s = (v >= 1.0f) ? 1.0f : 0.0f;
            v = (v >= 1.0f) ? 0.0f : v;
            float xv = __fadd_rn(cx[u], s);
            px[(long)(t0 + u) * DD] = xv;
            if (t0 + u == TT - 1) dout[b * DD + d] = xv;
        }
#pragma unroll
        for (int u = 0; u < U; ++u) { ci[u] = ni[u]; cx[u] = nx[u]; }
    }
}

// ---------------------------------------------------------------------------
// Launch
// ---------------------------------------------------------------------------
extern "C" void kernel_launch(void* const* d_in, const int* in_sizes, int n_in,
                              void* d_out, int out_size)
{
    const float* hist  = (const float*)d_in[0];
    const float* pw1   = (const float*)d_in[1];
    const float* pb1   = (const float*)d_in[2];
    const float* pw2   = (const float*)d_in[3];
    const float* pb2   = (const float*)d_in[4];
    const float* fc1_w = (const float*)d_in[5];
    const float* fc1_b = (const float*)d_in[6];
    const float* n1_g  = (const float*)d_in[7];
    const float* n1_b  = (const float*)d_in[8];
    const float* fc2_w = (const float*)d_in[9];
    const float* fc2_b = (const float*)d_in[10];
    const float* n2_g  = (const float*)d_in[11];
    const float* n2_b  = (const float*)d_in[12];
    float* out = (float*)d_out;

    float *px, *ph, *pt;
    uint32_t* pm;
    cudaGetSymbolAddress((void**)&px, g_x);
    cudaGetSymbolAddress((void**)&ph, g_h);
    cudaGetSymbolAddress((void**)&pt, g_t);
    cudaGetSymbolAddress((void**)&pm, g_m);

    // dynamic smem: max(mainloop, staging+stats)
    const int smem128 = (64 * 129 + 128) * 4;   // 33536 B
    const int smem256 = (64 * 257 + 128) * 4;   // 66304 B
    cudaFuncSetAttribute(gemm_ln_f2<DD, H0, false>,
                         cudaFuncAttributeMaxDynamicSharedMemorySize, smem128);
    cudaFuncSetAttribute(gemm_ln_f2<HDD, DD, true>,
                         cudaFuncAttributeMaxDynamicSharedMemorySize, smem256);
    cudaFuncSetAttribute(gemm_sparse_ln,
                         cudaFuncAttributeMaxDynamicSharedMemorySize, smem128);

    // Projector: hist@pw1 -> gelu -> @pw2 (+biases) -> g_x
    proj1_kernel<<<(MM * H0) / 256, 256>>>(hist, pw1, pb1, pt);
    gemm_ln_f2<DD, H0, false><<<MM / 64, 256, smem128>>>(pt, pw2, pb2, nullptr, nullptr, px);

    for (int i = 0; i < DEPTH; ++i) {
        gemm_ln_f2<HDD, DD, true><<<MM / 64, 256, smem256>>>(
            px, fc1_w + (long)i * DD * HDD, fc1_b + i * HDD,
            n1_g + i * HDD, n1_b + i * HDD, ph);
        lif_spike_kernel<<<(BB * HDD) / 64, 64>>>(ph, pm);
        gemm_sparse_ln<<<MM / 64, 256, smem128>>>(
            pm, fc2_w + (long)i * HDD * DD, fc2_b + i * DD,
            n2_g + i * DD, n2_b + i * DD, pt);
        lif_resid_kernel<<<(BB * DD) / 64, 64>>>(pt, px, out);
    }
}